// round 1
// baseline (speedup 1.0000x reference)
#include <cuda_runtime.h>

// Problem constants
#define B_  32
#define C_  256
#define O_  256
#define KS  7
#define KK  49      // 7*7
#define H_  31
#define W_  31
#define HO  25
#define WO  25
#define HW  625     // 25*25
#define CKK (C_*KK) // 12544

// Tiling
#define BLOCK_O 64
#define BLOCK_P 128
#define TO 4
#define TP 8
#define THREADS 256
#define NPT 5              // pixel tiles: ceil(625/128)
#define NOT 4              // o tiles: 256/64
#define WKPAD 68           // row stride for wk[kl][o] (68*4B = 272B, 16B aligned rows)
#define XROWS 12           // max input rows needed per pixel tile
#define XPITCH 32

__global__ __launch_bounds__(THREADS)
void dwconv_modulated_kernel(
    const float* __restrict__ x,      // [B,C,31,31]
    const float* __restrict__ kern,   // [B,C,7,7]
    const float* __restrict__ weight, // [O,C,7,7]
    const float* __restrict__ bias,   // [O]
    float* __restrict__ out)          // [B,O,25,25]
{
    const int blk = blockIdx.x;
    const int pt  = blk % NPT;
    const int ot  = (blk / NPT) % NOT;
    const int b   = blk / (NPT * NOT);

    const int p0 = pt * BLOCK_P;
    const int o0 = ot * BLOCK_O;

    const int tid = threadIdx.x;
    const int tx  = tid & 15;   // pixel group (0..15)
    const int ty  = tid >> 4;   // o group (0..15)

    __shared__ __align__(16) float xs[XROWS * XPITCH];
    __shared__ __align__(16) float wk[KK * WKPAD];   // [kl][o], padded

    // ---- per-block pixel geometry ----
    const int h_first = p0 / WO;
    const int p_last  = min(p0 + BLOCK_P - 1, HW - 1);
    const int h_last  = p_last / WO;
    const int nrows   = h_last - h_first + KS;   // input rows to stage (<= 12)

    int  pbase[TP];
    bool pvalid[TP];
    int  pidx[TP];
#pragma unroll
    for (int j = 0; j < TP; j++) {
        int p = p0 + tx + 16 * j;
        pvalid[j] = (p < HW);
        int pp = pvalid[j] ? p : p0;
        int ph = pp / WO;
        int pw = pp - ph * WO;
        pidx[j]  = pp;
        pbase[j] = (ph - h_first) * XPITCH + pw;
    }

    float acc[TO][TP];
#pragma unroll
    for (int oo = 0; oo < TO; oo++)
#pragma unroll
        for (int j = 0; j < TP; j++) acc[oo][j] = 0.0f;

    const float* xb = x    + (size_t)b * C_ * (H_ * W_);
    const float* kb = kern + (size_t)b * C_ * KK;
    const float* wb = weight + (size_t)o0 * CKK;

    for (int c = 0; c < C_; c++) {
        // ---- stage x rows [h_first, h_first+nrows) into smem ----
        const float* xc = xb + (size_t)c * (H_ * W_);
        const int nslots = nrows * XPITCH;
        for (int i = tid; i < nslots; i += THREADS) {
            int r   = i >> 5;
            int col = i & 31;
            if (col < W_) xs[i] = xc[(h_first + r) * W_ + col];
        }
        // ---- stage modulated weights wk[kl][o] = weight[o0+o,c,kl]*kernel[b,c,kl] ----
        const float* wc = wb + (size_t)c * KK;
        const float* kc = kb + (size_t)c * KK;
        for (int i = tid; i < KK * BLOCK_O; i += THREADS) {
            int o  = i / KK;
            int kl = i - o * KK;
            wk[kl * WKPAD + o] = wc[(size_t)o * CKK + kl] * __ldg(kc + kl);
        }
        __syncthreads();

        // ---- FMA mainloop ----
#pragma unroll
        for (int ki = 0; ki < KS; ki++) {
#pragma unroll
            for (int kj = 0; kj < KS; kj++) {
                const int kl = ki * KS + kj;
                const float4 w4 =
                    *reinterpret_cast<const float4*>(&wk[kl * WKPAD + ty * TO]);
                float xv[TP];
#pragma unroll
                for (int j = 0; j < TP; j++)
                    xv[j] = xs[pbase[j] + ki * XPITCH + kj];
#pragma unroll
                for (int j = 0; j < TP; j++) {
                    acc[0][j] += w4.x * xv[j];
                    acc[1][j] += w4.y * xv[j];
                    acc[2][j] += w4.z * xv[j];
                    acc[3][j] += w4.w * xv[j];
                }
            }
        }
        __syncthreads();
    }

    // ---- epilogue: bias + store ----
#pragma unroll
    for (int oo = 0; oo < TO; oo++) {
        const int o  = o0 + ty * TO + oo;
        const float bv = __ldg(bias + o);
        float* ob = out + ((size_t)b * O_ + o) * HW;
#pragma unroll
        for (int j = 0; j < TP; j++) {
            if (pvalid[j]) ob[pidx[j]] = acc[oo][j] + bv;
        }
    }
}

extern "C" void kernel_launch(void* const* d_in, const int* in_sizes, int n_in,
                              void* d_out, int out_size) {
    const float* x      = (const float*)d_in[0];
    const float* kernel = (const float*)d_in[1];
    const float* weight = (const float*)d_in[2];
    const float* bias   = (const float*)d_in[3];
    float* out = (float*)d_out;

    const int grid = B_ * NOT * NPT;   // 32*4*5 = 640 blocks
    dwconv_modulated_kernel<<<grid, THREADS>>>(x, kernel, weight, bias, out);
}